// round 1
// baseline (speedup 1.0000x reference)
#include <cuda_runtime.h>
#include <cuda_bf16.h>
#include <cstddef>

// DotAttention: B=16, T_dec=T_enc=1024, D=1024, fp32.
// out = [summaries (16M floats) | scores (16M floats)]
//
// Plan:
//   K1: S_exp = exp(SCALE * Q K^T)   (no max-subtraction needed: |logit| <~ 6)
//       -> writes unnormalized exp scores, per-(row, n-tile) partial sums
//   K2: scores /= rowsum             (in place)
//   K3: O = scores @ V               (reads normalized scores)

#define BATCH 16
#define TSEQ  1024
#define DDIM  1024
#define NTILES (TSEQ / 64)   // 16 column tiles per row

__constant__ float c_dummy; // (unused)

static constexpr float SCALE = 0.03125f; // 1/sqrt(1024)

// per-(global row, n-tile) partial row sums: [B*T][NTILES] = 1 MB
__device__ float g_rowpart[BATCH * TSEQ * NTILES];

// ---------------------------------------------------------------------------
// K1: 64x64 output tile of S = Q K^T (NT gemm, contract over contiguous D),
// then exp + partial row sums.
// ---------------------------------------------------------------------------
__global__ __launch_bounds__(256) void qk_exp_kernel(
    const float* __restrict__ Q,
    const float* __restrict__ K,
    float* __restrict__ scores)
{
    __shared__ float Qs[32][65];   // [k][m], +1 pad: conflict-free transpose
    __shared__ float Ks[32][65];   // [k][n]
    __shared__ float red[64][17];  // row-sum reduction

    const int tn = blockIdx.x;   // enc tile
    const int tm = blockIdx.y;   // dec tile
    const int b  = blockIdx.z;

    const int t  = threadIdx.x;
    const int tx = t & 15;
    const int ty = t >> 4;

    const float* Qb = Q + ((size_t)b * TSEQ + (size_t)tm * 64) * DDIM;
    const float* Kb = K + ((size_t)b * TSEQ + (size_t)tn * 64) * DDIM;

    float acc[4][4] = {};

    const int lrow = t >> 3;   // 0..31
    const int lc4  = t & 7;    // 0..7  (k offset = lc4*4)

    for (int k0 = 0; k0 < DDIM; k0 += 32) {
        // gmem loads (coalesced float4 along D)
        float4 qa = *(const float4*)(Qb + (size_t)lrow        * DDIM + k0 + lc4 * 4);
        float4 qb = *(const float4*)(Qb + (size_t)(lrow + 32) * DDIM + k0 + lc4 * 4);
        float4 ka = *(const float4*)(Kb + (size_t)lrow        * DDIM + k0 + lc4 * 4);
        float4 kb = *(const float4*)(Kb + (size_t)(lrow + 32) * DDIM + k0 + lc4 * 4);

        __syncthreads();   // previous compute done before overwrite
        Qs[lc4 * 4 + 0][lrow] = qa.x; Qs[lc4 * 4 + 1][lrow] = qa.y;
        Qs[lc4 * 4 + 2][lrow] = qa.z; Qs[lc4 * 4 + 3][lrow] = qa.w;
        Qs[lc4 * 4 + 0][lrow + 32] = qb.x; Qs[lc4 * 4 + 1][lrow + 32] = qb.y;
        Qs[lc4 * 4 + 2][lrow + 32] = qb.z; Qs[lc4 * 4 + 3][lrow + 32] = qb.w;
        Ks[lc4 * 4 + 0][lrow] = ka.x; Ks[lc4 * 4 + 1][lrow] = ka.y;
        Ks[lc4 * 4 + 2][lrow] = ka.z; Ks[lc4 * 4 + 3][lrow] = ka.w;
        Ks[lc4 * 4 + 0][lrow + 32] = kb.x; Ks[lc4 * 4 + 1][lrow + 32] = kb.y;
        Ks[lc4 * 4 + 2][lrow + 32] = kb.z; Ks[lc4 * 4 + 3][lrow + 32] = kb.w;
        __syncthreads();

        #pragma unroll
        for (int k = 0; k < 32; k++) {
            float a[4], bb[4];
            #pragma unroll
            for (int i = 0; i < 4; i++) a[i]  = Qs[k][ty + 16 * i];
            #pragma unroll
            for (int j = 0; j < 4; j++) bb[j] = Ks[k][tx + 16 * j];
            #pragma unroll
            for (int i = 0; i < 4; i++)
                #pragma unroll
                for (int j = 0; j < 4; j++)
                    acc[i][j] = fmaf(a[i], bb[j], acc[i][j]);
        }
    }

    // exp + per-thread row partials
    float rsum[4];
    #pragma unroll
    for (int i = 0; i < 4; i++) {
        float s = 0.f;
        #pragma unroll
        for (int j = 0; j < 4; j++) {
            float p = __expf(acc[i][j] * SCALE);
            acc[i][j] = p;
            s += p;
        }
        rsum[i] = s;
    }

    // write unnormalized exp scores
    float* Sb = scores + ((size_t)b * TSEQ + (size_t)tm * 64) * TSEQ + (size_t)tn * 64;
    #pragma unroll
    for (int i = 0; i < 4; i++)
        #pragma unroll
        for (int j = 0; j < 4; j++)
            Sb[(size_t)(ty + 16 * i) * TSEQ + (tx + 16 * j)] = acc[i][j];

    // reduce row partials across the 16 tx columns
    #pragma unroll
    for (int i = 0; i < 4; i++) red[ty + 16 * i][tx] = rsum[i];
    __syncthreads();
    if (t < 64) {
        float s = 0.f;
        #pragma unroll
        for (int x = 0; x < 16; x++) s += red[t][x];
        size_t grow = (size_t)b * TSEQ + (size_t)tm * 64 + t;
        g_rowpart[grow * NTILES + tn] = s;
    }
}

// ---------------------------------------------------------------------------
// K2: normalize one score row per block (1024 floats = 256 threads x float4)
// ---------------------------------------------------------------------------
__global__ __launch_bounds__(256) void norm_kernel(float* __restrict__ scores)
{
    const int row = blockIdx.x;   // b*1024 + m, 0..16383
    __shared__ float sinv;
    if (threadIdx.x == 0) {
        float s = 0.f;
        #pragma unroll
        for (int i = 0; i < NTILES; i++) s += g_rowpart[(size_t)row * NTILES + i];
        sinv = 1.0f / s;
    }
    __syncthreads();
    const float inv = sinv;
    float4* p = (float4*)(scores + (size_t)row * TSEQ);
    float4 v = p[threadIdx.x];
    v.x *= inv; v.y *= inv; v.z *= inv; v.w *= inv;
    p[threadIdx.x] = v;
}

// ---------------------------------------------------------------------------
// K3: O = P @ V (NN gemm: P row-major [M,K], V row-major [K,N]), 64x64 tiles
// ---------------------------------------------------------------------------
__global__ __launch_bounds__(256) void pv_kernel(
    const float* __restrict__ P,
    const float* __restrict__ V,
    float* __restrict__ O)
{
    __shared__ float Ps[32][65];   // [k][m] transposed
    __shared__ float Vs[32][64];   // [k][n] natural

    const int tn = blockIdx.x;
    const int tm = blockIdx.y;
    const int b  = blockIdx.z;

    const int t  = threadIdx.x;
    const int tx = t & 15;
    const int ty = t >> 4;

    const float* Pb = P + ((size_t)b * TSEQ + (size_t)tm * 64) * TSEQ;
    const float* Vb = V + (size_t)b * TSEQ * DDIM + (size_t)tn * 64;

    float acc[4][4] = {};

    const int lrow = t >> 3;   // P-tile: 0..31
    const int lc4  = t & 7;
    const int vrow = t >> 4;   // V-tile: 0..15
    const int vc4  = t & 15;

    for (int k0 = 0; k0 < TSEQ; k0 += 32) {
        float4 pa  = *(const float4*)(Pb + (size_t)lrow        * TSEQ + k0 + lc4 * 4);
        float4 pb2 = *(const float4*)(Pb + (size_t)(lrow + 32) * TSEQ + k0 + lc4 * 4);
        float4 va  = *(const float4*)(Vb + (size_t)(k0 + vrow)      * DDIM + vc4 * 4);
        float4 vb  = *(const float4*)(Vb + (size_t)(k0 + vrow + 16) * DDIM + vc4 * 4);

        __syncthreads();
        Ps[lc4 * 4 + 0][lrow] = pa.x; Ps[lc4 * 4 + 1][lrow] = pa.y;
        Ps[lc4 * 4 + 2][lrow] = pa.z; Ps[lc4 * 4 + 3][lrow] = pa.w;
        Ps[lc4 * 4 + 0][lrow + 32] = pb2.x; Ps[lc4 * 4 + 1][lrow + 32] = pb2.y;
        Ps[lc4 * 4 + 2][lrow + 32] = pb2.z; Ps[lc4 * 4 + 3][lrow + 32] = pb2.w;
        *(float4*)&Vs[vrow][vc4 * 4]      = va;
        *(float4*)&Vs[vrow + 16][vc4 * 4] = vb;
        __syncthreads();

        #pragma unroll
        for (int k = 0; k < 32; k++) {
            float a[4], bb[4];
            #pragma unroll
            for (int i = 0; i < 4; i++) a[i]  = Ps[k][ty + 16 * i];
            #pragma unroll
            for (int j = 0; j < 4; j++) bb[j] = Vs[k][tx + 16 * j];
            #pragma unroll
            for (int i = 0; i < 4; i++)
                #pragma unroll
                for (int j = 0; j < 4; j++)
                    acc[i][j] = fmaf(a[i], bb[j], acc[i][j]);
        }
    }

    float* Ob = O + ((size_t)b * TSEQ + (size_t)tm * 64) * DDIM + (size_t)tn * 64;
    #pragma unroll
    for (int i = 0; i < 4; i++)
        #pragma unroll
        for (int j = 0; j < 4; j++)
            Ob[(size_t)(ty + 16 * i) * DDIM + (tx + 16 * j)] = acc[i][j];
}

// ---------------------------------------------------------------------------
extern "C" void kernel_launch(void* const* d_in, const int* in_sizes, int n_in,
                              void* d_out, int out_size)
{
    const float* Q = (const float*)d_in[0];
    const float* K = (const float*)d_in[1];
    const float* V = (const float*)d_in[2];

    float* summaries = (float*)d_out;
    float* scores    = (float*)d_out + (size_t)BATCH * TSEQ * DDIM;

    dim3 grid(TSEQ / 64, TSEQ / 64, BATCH);   // (16,16,16)
    dim3 block(256);

    qk_exp_kernel<<<grid, block>>>(Q, K, scores);
    norm_kernel<<<BATCH * TSEQ, block>>>(scores);
    pv_kernel<<<grid, block>>>(scores, V, summaries);
}

// round 4
// speedup vs baseline: 3.6134x; 3.6134x over previous
#include <cuda_runtime.h>
#include <cuda_bf16.h>
#include <cstdint>
#include <cstddef>

// DotAttention B=16, T=1024, D=1024 fp32, compiled for plain sm_100 (no tcgen05).
// bf16 split-2 (hi/lo) GEMMs via arch-generic mma.sync.m16n8k16:
//   A*B ~= Ah*Bh + Ah*Bl + Al*Bh  (fp32 accumulate in registers)

#define BATCH 16
#define TSEQ  1024
#define DDIM  1024
#define NT    8            // 128-wide tiles per score row
static constexpr float SCALE = 0.03125f;

#define NELEM ((size_t)BATCH * TSEQ * DDIM)   // 16M

// scratch (module-static device arrays; no runtime allocation)
__device__ __align__(16) __nv_bfloat16 g_Qhi[NELEM];
__device__ __align__(16) __nv_bfloat16 g_Qlo[NELEM];
__device__ __align__(16) __nv_bfloat16 g_Khi[NELEM];
__device__ __align__(16) __nv_bfloat16 g_Klo[NELEM];
__device__ __align__(16) __nv_bfloat16 g_Vthi[NELEM];  // V^T per batch: [b][d][s]
__device__ __align__(16) __nv_bfloat16 g_Vtlo[NELEM];
__device__ __align__(16) __nv_bfloat16 g_Phi[NELEM];
__device__ __align__(16) __nv_bfloat16 g_Plo[NELEM];
__device__ float g_rowpart[BATCH * TSEQ * NT];

// ---------------------------------------------------------------------------
// helpers (all arch-generic PTX: sm_80+)
// ---------------------------------------------------------------------------
__device__ __forceinline__ uint32_t smem_u32(const void* p) {
    uint32_t a;
    asm("{ .reg .u64 t; cvta.to.shared.u64 t, %1; cvt.u32.u64 %0, t; }" : "=r"(a) : "l"(p));
    return a;
}
__device__ __forceinline__ void cp16(uint32_t dst, const void* src) {
    asm volatile("cp.async.cg.shared.global [%0], [%1], 16;" :: "r"(dst), "l"(src));
}
__device__ __forceinline__ void cp_commit() { asm volatile("cp.async.commit_group;" ::: "memory"); }
template <int N> __device__ __forceinline__ void cp_wait() {
    asm volatile("cp.async.wait_group %0;" :: "n"(N) : "memory");
}
__device__ __forceinline__ void ldsm4(uint32_t (&r)[4], uint32_t addr) {
    asm volatile("ldmatrix.sync.aligned.m8n8.x4.shared.b16 {%0,%1,%2,%3}, [%4];"
        : "=r"(r[0]), "=r"(r[1]), "=r"(r[2]), "=r"(r[3]) : "r"(addr));
}
__device__ __forceinline__ void mma16816(float (&d)[4], const uint32_t (&a)[4],
                                         uint32_t b0, uint32_t b1) {
    asm volatile(
        "mma.sync.aligned.m16n8k16.row.col.f32.bf16.bf16.f32 "
        "{%0,%1,%2,%3}, {%4,%5,%6,%7}, {%8,%9}, {%0,%1,%2,%3};"
        : "+f"(d[0]), "+f"(d[1]), "+f"(d[2]), "+f"(d[3])
        : "r"(a[0]), "r"(a[1]), "r"(a[2]), "r"(a[3]), "r"(b0), "r"(b1));
}
#define SW128(o) ((o) ^ (((o) >> 3) & 0x70))

// ---------------------------------------------------------------------------
// K0a/b: fp32 -> (hi, lo) bf16, elementwise (4 elems/thread)
// ---------------------------------------------------------------------------
template <int WHICH>  // 0: Q, 1: K
__global__ __launch_bounds__(256) void conv_hilo(const float* __restrict__ x) {
    __nv_bfloat16* hi = (WHICH == 0) ? g_Qhi : g_Khi;
    __nv_bfloat16* lo = (WHICH == 0) ? g_Qlo : g_Klo;
    size_t i = ((size_t)blockIdx.x * 256 + threadIdx.x) * 4;
    float4 v = *(const float4*)(x + i);
    __nv_bfloat16 h0 = __float2bfloat16(v.x), h1 = __float2bfloat16(v.y);
    __nv_bfloat16 h2 = __float2bfloat16(v.z), h3 = __float2bfloat16(v.w);
    __nv_bfloat16 l0 = __float2bfloat16(v.x - __bfloat162float(h0));
    __nv_bfloat16 l1 = __float2bfloat16(v.y - __bfloat162float(h1));
    __nv_bfloat16 l2 = __float2bfloat16(v.z - __bfloat162float(h2));
    __nv_bfloat16 l3 = __float2bfloat16(v.w - __bfloat162float(h3));
    __nv_bfloat162 hp0(h0, h1), hp1(h2, h3), lp0(l0, l1), lp1(l2, l3);
    *(uint2*)(hi + i) = make_uint2(*(uint32_t*)&hp0, *(uint32_t*)&hp1);
    *(uint2*)(lo + i) = make_uint2(*(uint32_t*)&lp0, *(uint32_t*)&lp1);
}

// ---------------------------------------------------------------------------
// K0c: V [b][s][d] -> V^T hi/lo [b][d][s]  (32x32 smem transpose tiles)
// ---------------------------------------------------------------------------
__global__ __launch_bounds__(256) void vtrans(const float* __restrict__ V) {
    __shared__ float tile[32][33];
    int b = blockIdx.z, s0 = blockIdx.y * 32, d0 = blockIdx.x * 32;
    int t = threadIdx.x;
    int r = t >> 3, c4 = t & 7;
    const float* Vb = V + ((size_t)b * TSEQ + s0) * DDIM + d0;
    float4 v = *(const float4*)(Vb + (size_t)r * DDIM + c4 * 4);
    tile[r][c4 * 4 + 0] = v.x; tile[r][c4 * 4 + 1] = v.y;
    tile[r][c4 * 4 + 2] = v.z; tile[r][c4 * 4 + 3] = v.w;
    __syncthreads();
    int dr = t >> 3, s4 = t & 7;
    float x0 = tile[s4 * 4 + 0][dr], x1 = tile[s4 * 4 + 1][dr];
    float x2 = tile[s4 * 4 + 2][dr], x3 = tile[s4 * 4 + 3][dr];
    __nv_bfloat16 h0 = __float2bfloat16(x0), h1 = __float2bfloat16(x1);
    __nv_bfloat16 h2 = __float2bfloat16(x2), h3 = __float2bfloat16(x3);
    __nv_bfloat16 l0 = __float2bfloat16(x0 - __bfloat162float(h0));
    __nv_bfloat16 l1 = __float2bfloat16(x1 - __bfloat162float(h1));
    __nv_bfloat16 l2 = __float2bfloat16(x2 - __bfloat162float(h2));
    __nv_bfloat16 l3 = __float2bfloat16(x3 - __bfloat162float(h3));
    size_t off = ((size_t)b * DDIM + d0 + dr) * TSEQ + s0 + s4 * 4;
    __nv_bfloat162 hp0(h0, h1), hp1(h2, h3), lp0(l0, l1), lp1(l2, l3);
    *(uint2*)(g_Vthi + off) = make_uint2(*(uint32_t*)&hp0, *(uint32_t*)&hp1);
    *(uint2*)(g_Vtlo + off) = make_uint2(*(uint32_t*)&lp0, *(uint32_t*)&lp1);
}

// ---------------------------------------------------------------------------
// GEMM core: C[128,128] fp32 = A[128,1024] x B[128,1024]^T (both K-major, hi/lo split)
// via mma.sync.m16n8k16. 8 warps = 2(m) x 4(n); warp tile 64x32.
// MODE 0: QK^T -> exp -> scores + row partial sums.  MODE 1: PV -> summaries.
// Smem: 2 stages x { Ah, Al, Bh, Bl : 128 rows x 128B (64 bf16), SW128 }.
// ---------------------------------------------------------------------------
#define SMEM_SZ 131072       // 2 * 64KB stages; epilogue staging reuses it
#define RED_OFF 69632        // past 128x132 f32 stage area (67584B)

template <int MODE>
__global__ void __launch_bounds__(256, 1) gemm_kernel(float* __restrict__ out) {
    extern __shared__ __align__(1024) char smem[];
    const uint32_t sb = smem_u32(smem);
    const int t = threadIdx.x, wid = t >> 5, lane = t & 31;
    const int tn = blockIdx.x, tm = blockIdx.y, b = blockIdx.z;

    const __nv_bfloat16 *Ahi, *Alo, *Bhi, *Blo;
    if (MODE == 0) { Ahi = g_Qhi; Alo = g_Qlo; Bhi = g_Khi; Blo = g_Klo; }
    else           { Ahi = g_Phi; Alo = g_Plo; Bhi = g_Vthi; Blo = g_Vtlo; }

    const size_t aoff = ((size_t)b * TSEQ + tm * 128) * 1024;
    const size_t boff = ((size_t)b * TSEQ + tn * 128) * 1024;
    const __nv_bfloat16* Ah = Ahi + aoff;
    const __nv_bfloat16* Al = Alo + aoff;
    const __nv_bfloat16* Bh = Bhi + boff;
    const __nv_bfloat16* Bl = Blo + boff;

    // ---- producer: cp.async into SW128-swizzled 128B rows (64 bf16 = k-chunk) ----
    const int lr = t >> 3;          // 0..31 base row
    const int lc = t & 7;           // 16B chunk within 128B row
    const uint32_t dsw = SW128((uint32_t)(lr * 128 + lc * 16));  // +32 rows adds 4096 (swizzle-invariant)

    auto load_stage = [&](int st, int k0) {
        const uint32_t s0 = sb + st * 65536;
        const __nv_bfloat16* srcs[4] = {Ah, Al, Bh, Bl};
        #pragma unroll
        for (int buf = 0; buf < 4; buf++) {
            const __nv_bfloat16* p = srcs[buf] + k0 + lc * 8;
            #pragma unroll
            for (int j = 0; j < 4; j++)
                cp16(s0 + buf * 16384 + dsw + j * 4096, p + (size_t)(lr + 32 * j) * 1024);
        }
        cp_commit();
    };

    // ---- consumer fragment addressing ----
    const int warp_m = wid >> 2;          // 0..1  (64 rows)
    const int warp_n = wid & 3;           // 0..3  (32 cols)
    const int mrow = lane & 7, mid = lane >> 3;
    const int arow_base = warp_m * 64 + mrow + (mid & 1) * 8;
    const int a_k8 = mid >> 1;
    const int brow_base = warp_n * 32 + mrow + (mid >> 1) * 8;
    const int b_k8 = mid & 1;

    float acc[4][4][4] = {};

    load_stage(0, 0);
    load_stage(1, 64);

    for (int i = 0; i < 16; i++) {
        const int st = i & 1;
        if (i == 15) cp_wait<0>(); else cp_wait<1>();
        __syncthreads();

        const uint32_t sA_h = sb + st * 65536;
        const uint32_t sA_l = sA_h + 16384;
        const uint32_t sB_h = sA_h + 32768;
        const uint32_t sB_l = sA_h + 49152;

        #pragma unroll
        for (int ks = 0; ks < 4; ks++) {
            uint32_t ah[4][4], al[4][4], bh[2][4], bl[2][4];
            #pragma unroll
            for (int mt = 0; mt < 4; mt++) {
                uint32_t off = SW128((uint32_t)((arow_base + mt * 16) * 128 + (ks * 2 + a_k8) * 16));
                ldsm4(ah[mt], sA_h + off);
                ldsm4(al[mt], sA_l + off);
            }
            #pragma unroll
            for (int np = 0; np < 2; np++) {
                uint32_t off = SW128((uint32_t)((brow_base + np * 16) * 128 + (ks * 2 + b_k8) * 16));
                ldsm4(bh[np], sB_h + off);
                ldsm4(bl[np], sB_l + off);
            }
            #pragma unroll
            for (int mt = 0; mt < 4; mt++)
                #pragma unroll
                for (int nt = 0; nt < 4; nt++) {
                    const int np = nt >> 1, h = (nt & 1) * 2;
                    mma16816(acc[mt][nt], ah[mt], bh[np][h], bh[np][h + 1]);
                    mma16816(acc[mt][nt], ah[mt], bl[np][h], bl[np][h + 1]);
                    mma16816(acc[mt][nt], al[mt], bh[np][h], bh[np][h + 1]);
                }
        }

        __syncthreads();
        if (i + 2 < 16) load_stage(st, (i + 2) * 64);
    }

    __syncthreads();   // smem now free for epilogue staging

    // ---- epilogue ----
    // C layout per mma: d0=(r0,c) d1=(r0,c+1) d2=(r0+8,c) d3=(r0+8,c+1);
    // r0 = warp_m*64 + mt*16 + lane/4, c = warp_n*32 + nt*8 + (lane%4)*2
    const int quad = lane >> 2, qid = lane & 3;
    float* stage = (float*)smem;                 // pitch 132 floats
    float* red = (float*)(smem + RED_OFF);       // [128][4]

    float rs0[4] = {}, rs1[4] = {};
    #pragma unroll
    for (int mt = 0; mt < 4; mt++) {
        const int r0 = warp_m * 64 + mt * 16 + quad;
        #pragma unroll
        for (int nt = 0; nt < 4; nt++) {
            const int c = warp_n * 32 + nt * 8 + qid * 2;
            float d0 = acc[mt][nt][0], d1 = acc[mt][nt][1];
            float d2 = acc[mt][nt][2], d3 = acc[mt][nt][3];
            if (MODE == 0) {
                d0 = __expf(d0 * SCALE); d1 = __expf(d1 * SCALE);
                d2 = __expf(d2 * SCALE); d3 = __expf(d3 * SCALE);
                rs0[mt] += d0 + d1; rs1[mt] += d2 + d3;
            }
            *(float2*)&stage[r0 * 132 + c]       = make_float2(d0, d1);
            *(float2*)&stage[(r0 + 8) * 132 + c] = make_float2(d2, d3);
        }
    }
    if (MODE == 0) {
        #pragma unroll
        for (int mt = 0; mt < 4; mt++) {
            float s0 = rs0[mt], s1 = rs1[mt];
            s0 += __shfl_xor_sync(0xFFFFFFFFu, s0, 1);
            s0 += __shfl_xor_sync(0xFFFFFFFFu, s0, 2);
            s1 += __shfl_xor_sync(0xFFFFFFFFu, s1, 1);
            s1 += __shfl_xor_sync(0xFFFFFFFFu, s1, 2);
            if (qid == 0) {
                const int r0 = warp_m * 64 + mt * 16 + quad;
                red[r0 * 4 + warp_n] = s0;
                red[(r0 + 8) * 4 + warp_n] = s1;
            }
        }
    }
    __syncthreads();

    if (MODE == 0 && t < 128) {
        float s = red[t * 4 + 0] + red[t * 4 + 1] + red[t * 4 + 2] + red[t * 4 + 3];
        g_rowpart[((size_t)b * TSEQ + tm * 128 + t) * NT + tn] = s;
    }

    float* op = out + ((size_t)b * TSEQ + tm * 128) * 1024 + tn * 128;
    const int j = t & 31;
    #pragma unroll
    for (int r = t >> 5; r < 128; r += 8) {
        float4 v = *(float4*)&stage[r * 132 + j * 4];
        *(float4*)(op + (size_t)r * 1024 + j * 4) = v;
    }
}

// ---------------------------------------------------------------------------
// K2: normalize scores row, emit P hi/lo
// ---------------------------------------------------------------------------
__global__ __launch_bounds__(256) void norm_kernel(float* __restrict__ scores) {
    const int row = blockIdx.x;
    __shared__ float sinv;
    if (threadIdx.x < 8) {
        float s = g_rowpart[(size_t)row * NT + threadIdx.x];
        #pragma unroll
        for (int o = 4; o > 0; o >>= 1) s += __shfl_xor_sync(0xFFu, s, o);
        if (threadIdx.x == 0) sinv = 1.0f / s;
    }
    __syncthreads();
    const float inv = sinv;
    const size_t base = (size_t)row * TSEQ + threadIdx.x * 4;
    float4 v = *(float4*)(scores + base);
    v.x *= inv; v.y *= inv; v.z *= inv; v.w *= inv;
    *(float4*)(scores + base) = v;
    __nv_bfloat16 h0 = __float2bfloat16(v.x), h1 = __float2bfloat16(v.y);
    __nv_bfloat16 h2 = __float2bfloat16(v.z), h3 = __float2bfloat16(v.w);
    __nv_bfloat16 l0 = __float2bfloat16(v.x - __bfloat162float(h0));
    __nv_bfloat16 l1 = __float2bfloat16(v.y - __bfloat162float(h1));
    __nv_bfloat16 l2 = __float2bfloat16(v.z - __bfloat162float(h2));
    __nv_bfloat16 l3 = __float2bfloat16(v.w - __bfloat162float(h3));
    __nv_bfloat162 hp0(h0, h1), hp1(h2, h3), lp0(l0, l1), lp1(l2, l3);
    *(uint2*)(g_Phi + base) = make_uint2(*(uint32_t*)&hp0, *(uint32_t*)&hp1);
    *(uint2*)(g_Plo + base) = make_uint2(*(uint32_t*)&lp0, *(uint32_t*)&lp1);
}

// ---------------------------------------------------------------------------
extern "C" void kernel_launch(void* const* d_in, const int* in_sizes, int n_in,
                              void* d_out, int out_size)
{
    const float* Q = (const float*)d_in[0];
    const float* K = (const float*)d_in[1];
    const float* V = (const float*)d_in[2];
    float* summaries = (float*)d_out;
    float* scores    = (float*)d_out + NELEM;

    cudaFuncSetAttribute(gemm_kernel<0>, cudaFuncAttributeMaxDynamicSharedMemorySize, SMEM_SZ);
    cudaFuncSetAttribute(gemm_kernel<1>, cudaFuncAttributeMaxDynamicSharedMemorySize, SMEM_SZ);

    const int cblocks = (int)(NELEM / (256 * 4));
    conv_hilo<0><<<cblocks, 256>>>(Q);
    conv_hilo<1><<<cblocks, 256>>>(K);
    vtrans<<<dim3(32, 32, 16), 256>>>(V);

    dim3 ggrid(8, 8, 16);
    gemm_kernel<0><<<ggrid, 256, SMEM_SZ>>>(scores);
    norm_kernel<<<BATCH * TSEQ, 256>>>(scores);
    gemm_kernel<1><<<ggrid, 256, SMEM_SZ>>>(summaries);
}

// round 6
// speedup vs baseline: 4.9549x; 1.3713x over previous
#include <cuda_runtime.h>
#include <cuda_bf16.h>
#include <cuda_fp16.h>
#include <cstdint>
#include <cstddef>

// DotAttention B=16, T=1024, D=1024 fp32 (plain sm_100, mma.sync path).
// QK^T: bf16 split-2 (Ah*Bh + Ah*Bl + Al*Bh), 3-stage pipeline.
// P*V : fp16 single-pass (error ~4e-4, within 1e-3), 2 CTAs/SM.

#define BATCH 16
#define TSEQ  1024
#define DDIM  1024
#define NT    8
static constexpr float SCALE = 0.03125f;

#define NELEM ((size_t)BATCH * TSEQ * DDIM)   // 16M

__device__ __align__(16) __nv_bfloat16 g_Qhi[NELEM];
__device__ __align__(16) __nv_bfloat16 g_Qlo[NELEM];
__device__ __align__(16) __nv_bfloat16 g_Khi[NELEM];
__device__ __align__(16) __nv_bfloat16 g_Klo[NELEM];
__device__ __align__(16) __half       g_Vtf16[NELEM];  // V^T per batch: [b][d][s]
__device__ __align__(16) __half       g_Pf16[NELEM];   // normalized P fp16
__device__ float g_rowpart[BATCH * TSEQ * NT];

// ---------------------------------------------------------------------------
__device__ __forceinline__ uint32_t smem_u32(const void* p) {
    uint32_t a;
    asm("{ .reg .u64 t; cvta.to.shared.u64 t, %1; cvt.u32.u64 %0, t; }" : "=r"(a) : "l"(p));
    return a;
}
__device__ __forceinline__ void cp16(uint32_t dst, const void* src) {
    asm volatile("cp.async.cg.shared.global [%0], [%1], 16;" :: "r"(dst), "l"(src));
}
__device__ __forceinline__ void cp_commit() { asm volatile("cp.async.commit_group;" ::: "memory"); }
template <int N> __device__ __forceinline__ void cp_wait() {
    asm volatile("cp.async.wait_group %0;" :: "n"(N) : "memory");
}
__device__ __forceinline__ void ldsm4(uint32_t (&r)[4], uint32_t addr) {
    asm volatile("ldmatrix.sync.aligned.m8n8.x4.shared.b16 {%0,%1,%2,%3}, [%4];"
        : "=r"(r[0]), "=r"(r[1]), "=r"(r[2]), "=r"(r[3]) : "r"(addr));
}
__device__ __forceinline__ void mma_bf16(float (&d)[4], const uint32_t (&a)[4],
                                         uint32_t b0, uint32_t b1) {
    asm volatile(
        "mma.sync.aligned.m16n8k16.row.col.f32.bf16.bf16.f32 "
        "{%0,%1,%2,%3}, {%4,%5,%6,%7}, {%8,%9}, {%0,%1,%2,%3};"
        : "+f"(d[0]), "+f"(d[1]), "+f"(d[2]), "+f"(d[3])
        : "r"(a[0]), "r"(a[1]), "r"(a[2]), "r"(a[3]), "r"(b0), "r"(b1));
}
__device__ __forceinline__ void mma_f16(float (&d)[4], const uint32_t (&a)[4],
                                        uint32_t b0, uint32_t b1) {
    asm volatile(
        "mma.sync.aligned.m16n8k16.row.col.f32.f16.f16.f32 "
        "{%0,%1,%2,%3}, {%4,%5,%6,%7}, {%8,%9}, {%0,%1,%2,%3};"
        : "+f"(d[0]), "+f"(d[1]), "+f"(d[2]), "+f"(d[3])
        : "r"(a[0]), "r"(a[1]), "r"(a[2]), "r"(a[3]), "r"(b0), "r"(b1));
}
#define SW128(o) ((o) ^ (((o) >> 3) & 0x70))

// ---------------------------------------------------------------------------
// conv: fp32 -> (hi, lo) bf16
// ---------------------------------------------------------------------------
template <int WHICH>
__global__ __launch_bounds__(256) void conv_hilo(const float* __restrict__ x) {
    __nv_bfloat16* hi = (WHICH == 0) ? g_Qhi : g_Khi;
    __nv_bfloat16* lo = (WHICH == 0) ? g_Qlo : g_Klo;
    size_t i = ((size_t)blockIdx.x * 256 + threadIdx.x) * 4;
    float4 v = *(const float4*)(x + i);
    __nv_bfloat16 h0 = __float2bfloat16(v.x), h1 = __float2bfloat16(v.y);
    __nv_bfloat16 h2 = __float2bfloat16(v.z), h3 = __float2bfloat16(v.w);
    __nv_bfloat16 l0 = __float2bfloat16(v.x - __bfloat162float(h0));
    __nv_bfloat16 l1 = __float2bfloat16(v.y - __bfloat162float(h1));
    __nv_bfloat16 l2 = __float2bfloat16(v.z - __bfloat162float(h2));
    __nv_bfloat16 l3 = __float2bfloat16(v.w - __bfloat162float(h3));
    __nv_bfloat162 hp0(h0, h1), hp1(h2, h3), lp0(l0, l1), lp1(l2, l3);
    *(uint2*)(hi + i) = make_uint2(*(uint32_t*)&hp0, *(uint32_t*)&hp1);
    *(uint2*)(lo + i) = make_uint2(*(uint32_t*)&lp0, *(uint32_t*)&lp1);
}

// ---------------------------------------------------------------------------
// vtrans: V [b][s][d] -> V^T fp16 [b][d][s]
// ---------------------------------------------------------------------------
__global__ __launch_bounds__(256) void vtrans(const float* __restrict__ V) {
    __shared__ float tile[32][33];
    int b = blockIdx.z, s0 = blockIdx.y * 32, d0 = blockIdx.x * 32;
    int t = threadIdx.x;
    int r = t >> 3, c4 = t & 7;
    const float* Vb = V + ((size_t)b * TSEQ + s0) * DDIM + d0;
    float4 v = *(const float4*)(Vb + (size_t)r * DDIM + c4 * 4);
    tile[r][c4 * 4 + 0] = v.x; tile[r][c4 * 4 + 1] = v.y;
    tile[r][c4 * 4 + 2] = v.z; tile[r][c4 * 4 + 3] = v.w;
    __syncthreads();
    int dr = t >> 3, s4 = t & 7;
    float x0 = tile[s4 * 4 + 0][dr], x1 = tile[s4 * 4 + 1][dr];
    float x2 = tile[s4 * 4 + 2][dr], x3 = tile[s4 * 4 + 3][dr];
    __half2 p0 = __floats2half2_rn(x0, x1);
    __half2 p1 = __floats2half2_rn(x2, x3);
    size_t off = ((size_t)b * DDIM + d0 + dr) * TSEQ + s0 + s4 * 4;
    *(uint2*)(g_Vtf16 + off) = make_uint2(*(uint32_t*)&p0, *(uint32_t*)&p1);
}

// ---------------------------------------------------------------------------
// QK^T: C[128,128] = Q[128,1024] K[128,1024]^T, bf16 3-term split.
// 3-stage k64 pipeline (192KB smem), 8 warps = 2m x 4n, warp tile 64x32.
// Epilogue: exp, row partial sums, staged coalesced store.
// ---------------------------------------------------------------------------
#define QK_SMEM (3 * 65536 + 2048)
#define QK_RED  (3 * 65536)

__global__ void __launch_bounds__(256, 1) qk_gemm(float* __restrict__ out) {
    extern __shared__ __align__(1024) char smem[];
    const uint32_t sb = smem_u32(smem);
    const int t = threadIdx.x, wid = t >> 5, lane = t & 31;
    const int tn = blockIdx.x, tm = blockIdx.y, b = blockIdx.z;

    const size_t aoff = ((size_t)b * TSEQ + tm * 128) * 1024;
    const size_t boff = ((size_t)b * TSEQ + tn * 128) * 1024;
    const __nv_bfloat16* srcs[4] = {g_Qhi + aoff, g_Qlo + aoff, g_Khi + boff, g_Klo + boff};

    const int lr = t >> 3;
    const int lc = t & 7;
    const uint32_t dsw = SW128((uint32_t)(lr * 128 + lc * 16));

    auto load_stage = [&](int slot, int k0) {
        const uint32_t s0 = sb + slot * 65536;
        #pragma unroll
        for (int buf = 0; buf < 4; buf++) {
            const __nv_bfloat16* p = srcs[buf] + k0 + lc * 8;
            #pragma unroll
            for (int j = 0; j < 4; j++)
                cp16(s0 + buf * 16384 + dsw + j * 4096, p + (size_t)(lr + 32 * j) * 1024);
        }
        cp_commit();
    };

    const int warp_m = wid >> 2, warp_n = wid & 3;
    const int mrow = lane & 7, mid = lane >> 3;
    const int arow_base = warp_m * 64 + mrow + (mid & 1) * 8;
    const int a_k8 = mid >> 1;
    const int brow_base = warp_n * 32 + mrow + (mid >> 1) * 8;
    const int b_k8 = mid & 1;

    float acc[4][4][4] = {};

    load_stage(0, 0);
    load_stage(1, 64);

    for (int i = 0; i < 16; i++) {
        if (i == 15) cp_wait<0>(); else cp_wait<1>();
        __syncthreads();
        if (i + 2 < 16) load_stage((i + 2) % 3, (i + 2) * 64);   // slot freed at i-1

        const uint32_t sA_h = sb + (i % 3) * 65536;
        const uint32_t sA_l = sA_h + 16384;
        const uint32_t sB_h = sA_h + 32768;
        const uint32_t sB_l = sA_h + 49152;

        #pragma unroll
        for (int ks = 0; ks < 4; ks++) {
            uint32_t ah[4][4], al[4][4], bh[2][4], bl[2][4];
            #pragma unroll
            for (int mt = 0; mt < 4; mt++) {
                uint32_t off = SW128((uint32_t)((arow_base + mt * 16) * 128 + (ks * 2 + a_k8) * 16));
                ldsm4(ah[mt], sA_h + off);
                ldsm4(al[mt], sA_l + off);
            }
            #pragma unroll
            for (int np = 0; np < 2; np++) {
                uint32_t off = SW128((uint32_t)((brow_base + np * 16) * 128 + (ks * 2 + b_k8) * 16));
                ldsm4(bh[np], sB_h + off);
                ldsm4(bl[np], sB_l + off);
            }
            #pragma unroll
            for (int mt = 0; mt < 4; mt++)
                #pragma unroll
                for (int nt = 0; nt < 4; nt++) {
                    const int np = nt >> 1, h = (nt & 1) * 2;
                    mma_bf16(acc[mt][nt], ah[mt], bh[np][h], bh[np][h + 1]);
                    mma_bf16(acc[mt][nt], ah[mt], bl[np][h], bl[np][h + 1]);
                    mma_bf16(acc[mt][nt], al[mt], bh[np][h], bh[np][h + 1]);
                }
        }
    }

    __syncthreads();   // all MMA reads done; stage area reusable

    const int quad = lane >> 2, qid = lane & 3;
    float* stage = (float*)smem;                 // pitch 132 floats
    float* red = (float*)(smem + QK_RED);        // [128][4]

    float rs0[4] = {}, rs1[4] = {};
    #pragma unroll
    for (int mt = 0; mt < 4; mt++) {
        const int r0 = warp_m * 64 + mt * 16 + quad;
        #pragma unroll
        for (int nt = 0; nt < 4; nt++) {
            const int c = warp_n * 32 + nt * 8 + qid * 2;
            float d0 = __expf(acc[mt][nt][0] * SCALE);
            float d1 = __expf(acc[mt][nt][1] * SCALE);
            float d2 = __expf(acc[mt][nt][2] * SCALE);
            float d3 = __expf(acc[mt][nt][3] * SCALE);
            rs0[mt] += d0 + d1; rs1[mt] += d2 + d3;
            *(float2*)&stage[r0 * 132 + c]       = make_float2(d0, d1);
            *(float2*)&stage[(r0 + 8) * 132 + c] = make_float2(d2, d3);
        }
    }
    #pragma unroll
    for (int mt = 0; mt < 4; mt++) {
        float s0 = rs0[mt], s1 = rs1[mt];
        s0 += __shfl_xor_sync(0xFFFFFFFFu, s0, 1);
        s0 += __shfl_xor_sync(0xFFFFFFFFu, s0, 2);
        s1 += __shfl_xor_sync(0xFFFFFFFFu, s1, 1);
        s1 += __shfl_xor_sync(0xFFFFFFFFu, s1, 2);
        if (qid == 0) {
            const int r0 = warp_m * 64 + mt * 16 + quad;
            red[r0 * 4 + warp_n] = s0;
            red[(r0 + 8) * 4 + warp_n] = s1;
        }
    }
    __syncthreads();

    if (t < 128) {
        float s = red[t * 4 + 0] + red[t * 4 + 1] + red[t * 4 + 2] + red[t * 4 + 3];
        g_rowpart[((size_t)b * TSEQ + tm * 128 + t) * NT + tn] = s;
    }

    float* op = out + ((size_t)b * TSEQ + tm * 128) * 1024 + tn * 128;
    const int j = t & 31;
    #pragma unroll
    for (int r = t >> 5; r < 128; r += 8) {
        float4 v = *(float4*)&stage[r * 132 + j * 4];
        *(float4*)(op + (size_t)r * 1024 + j * 4) = v;
    }
}

// ---------------------------------------------------------------------------
// P*V: O[128,128] = P[128,1024] Vt[128,1024]^T, fp16 single-pass.
// 2-stage k64 (64KB smem), 2 CTAs/SM, direct register->gmem epilogue.
// ---------------------------------------------------------------------------
#define PV_SMEM 65536

__global__ void __launch_bounds__(256, 2) pv_gemm(float* __restrict__ out) {
    extern __shared__ __align__(1024) char smem[];
    const uint32_t sb = smem_u32(smem);
    const int t = threadIdx.x, wid = t >> 5, lane = t & 31;
    const int tn = blockIdx.x, tm = blockIdx.y, b = blockIdx.z;

    const __half* srcs[2] = {
        g_Pf16  + ((size_t)b * TSEQ + tm * 128) * 1024,
        g_Vtf16 + ((size_t)b * DDIM + tn * 128) * 1024
    };

    const int lr = t >> 3;
    const int lc = t & 7;
    const uint32_t dsw = SW128((uint32_t)(lr * 128 + lc * 16));

    auto load_stage = [&](int slot, int k0) {
        const uint32_t s0 = sb + slot * 32768;
        #pragma unroll
        for (int buf = 0; buf < 2; buf++) {
            const __half* p = srcs[buf] + k0 + lc * 8;
            #pragma unroll
            for (int j = 0; j < 4; j++)
                cp16(s0 + buf * 16384 + dsw + j * 4096, p + (size_t)(lr + 32 * j) * 1024);
        }
        cp_commit();
    };

    const int warp_m = wid >> 2, warp_n = wid & 3;
    const int mrow = lane & 7, mid = lane >> 3;
    const int arow_base = warp_m * 64 + mrow + (mid & 1) * 8;
    const int a_k8 = mid >> 1;
    const int brow_base = warp_n * 32 + mrow + (mid >> 1) * 8;
    const int b_k8 = mid & 1;

    float acc[4][4][4] = {};

    load_stage(0, 0);
    load_stage(1, 64);

    for (int i = 0; i < 16; i++) {
        if (i == 15) cp_wait<0>(); else cp_wait<1>();
        __syncthreads();

        const uint32_t sA = sb + (i & 1) * 32768;
        const uint32_t sB = sA + 16384;

        #pragma unroll
        for (int ks = 0; ks < 4; ks++) {
            uint32_t ah[4][4], bh[2][4];
            #pragma unroll
            for (int mt = 0; mt < 4; mt++) {
                uint32_t off = SW128((uint32_t)((arow_base + mt * 16) * 128 + (ks * 2 + a_k8) * 16));
                ldsm4(ah[mt], sA + off);
            }
            #pragma unroll
            for (int np = 0; np < 2; np++) {
                uint32_t off = SW128((uint32_t)((brow_base + np * 16) * 128 + (ks * 2 + b_k8) * 16));
                ldsm4(bh[np], sB + off);
            }
            #pragma unroll
            for (int mt = 0; mt < 4; mt++)
                #pragma unroll
                for (int nt = 0; nt < 4; nt++) {
                    const int np = nt >> 1, h = (nt & 1) * 2;
                    mma_f16(acc[mt][nt], ah[mt], bh[np][h], bh[np][h + 1]);
                }
        }

        __syncthreads();
        if (i + 2 < 16) load_stage(i & 1, (i + 2) * 64);
    }

    // direct register -> gmem epilogue
    const int quad = lane >> 2, qid = lane & 3;
    float* op = out + ((size_t)b * TSEQ + tm * 128) * 1024 + tn * 128;
    #pragma unroll
    for (int mt = 0; mt < 4; mt++) {
        const int r0 = warp_m * 64 + mt * 16 + quad;
        #pragma unroll
        for (int nt = 0; nt < 4; nt++) {
            const int c = warp_n * 32 + nt * 8 + qid * 2;
            *(float2*)(op + (size_t)r0 * 1024 + c)       = make_float2(acc[mt][nt][0], acc[mt][nt][1]);
            *(float2*)(op + (size_t)(r0 + 8) * 1024 + c) = make_float2(acc[mt][nt][2], acc[mt][nt][3]);
        }
    }
}

// ---------------------------------------------------------------------------
// norm: scores /= rowsum (fp32 in place), emit fp16 P
// ---------------------------------------------------------------------------
__global__ __launch_bounds__(256) void norm_kernel(float* __restrict__ scores) {
    const int row = blockIdx.x;
    __shared__ float sinv;
    if (threadIdx.x < 8) {
        float s = g_rowpart[(size_t)row * NT + threadIdx.x];
        #pragma unroll
        for (int o = 4; o > 0; o >>= 1) s += __shfl_xor_sync(0xFFu, s, o);
        if (threadIdx.x == 0) sinv = 1.0f / s;
    }
    __syncthreads();
    const float inv = sinv;
    const size_t base = (size_t)row * TSEQ + threadIdx.x * 4;
    float4 v = *(float4*)(scores + base);
    v.x *= inv; v.y *= inv; v.z *= inv; v.w *= inv;
    *(float4*)(scores + base) = v;
    __half2 p0 = __floats2half2_rn(v.x, v.y);
    __half2 p1 = __floats2half2_rn(v.z, v.w);
    *(uint2*)(g_Pf16 + base) = make_uint2(*(uint32_t*)&p0, *(uint32_t*)&p1);
}

// ---------------------------------------------------------------------------
extern "C" void kernel_launch(void* const* d_in, const int* in_sizes, int n_in,
                              void* d_out, int out_size)
{
    const float* Q = (const float*)d_in[0];
    const float* K = (const float*)d_in[1];
    const float* V = (const float*)d_in[2];
    float* summaries = (float*)d_out;
    float* scores    = (float*)d_out + NELEM;

    cudaFuncSetAttribute(qk_gemm, cudaFuncAttributeMaxDynamicSharedMemorySize, QK_SMEM);
    cudaFuncSetAttribute(pv_gemm, cudaFuncAttributeMaxDynamicSharedMemorySize, PV_SMEM);

    const int cblocks = (int)(NELEM / (256 * 4));
    conv_hilo<0><<<cblocks, 256>>>(Q);
    conv_hilo<1><<<cblocks, 256>>>(K);
    vtrans<<<dim3(32, 32, 16), 256>>>(V);

    dim3 ggrid(8, 8, 16);
    qk_gemm<<<ggrid, 256, QK_SMEM>>>(scores);
    norm_kernel<<<BATCH * TSEQ, 256>>>(scores);
    pv_gemm<<<ggrid, 256, PV_SMEM>>>(summaries);
}

// round 8
// speedup vs baseline: 5.9813x; 1.2072x over previous
#include <cuda_runtime.h>
#include <cuda_bf16.h>
#include <cuda_fp16.h>
#include <cstdint>
#include <cstddef>

// DotAttention B=16, T=1024, D=1024 fp32 (plain sm_100, mma.sync path).
// QK^T: fp16 2-term (Qh*Kh + Ql*Kh), K single fp16. scores err ~2.8e-4.
// P*V : fp16 single-pass. summaries err ~4e-4. Total < 1e-3.

#define BATCH 16
#define TSEQ  1024
#define DDIM  1024
#define NT    8
static constexpr float SCALE = 0.03125f;

#define NELEM ((size_t)BATCH * TSEQ * DDIM)   // 16M

__device__ __align__(16) __half g_Qhi[NELEM];
__device__ __align__(16) __half g_Qlo[NELEM];
__device__ __align__(16) __half g_Kf16[NELEM];
__device__ __align__(16) __half g_Vtf16[NELEM];  // V^T per batch: [b][d][s]
__device__ __align__(16) __half g_Pf16[NELEM];   // normalized P fp16
__device__ float g_rowpart[BATCH * TSEQ * NT];

// ---------------------------------------------------------------------------
__device__ __forceinline__ uint32_t smem_u32(const void* p) {
    uint32_t a;
    asm("{ .reg .u64 t; cvta.to.shared.u64 t, %1; cvt.u32.u64 %0, t; }" : "=r"(a) : "l"(p));
    return a;
}
__device__ __forceinline__ void cp16(uint32_t dst, const void* src) {
    asm volatile("cp.async.cg.shared.global [%0], [%1], 16;" :: "r"(dst), "l"(src));
}
__device__ __forceinline__ void cp_commit() { asm volatile("cp.async.commit_group;" ::: "memory"); }
template <int N> __device__ __forceinline__ void cp_wait() {
    asm volatile("cp.async.wait_group %0;" :: "n"(N) : "memory");
}
__device__ __forceinline__ void ldsm4(uint32_t (&r)[4], uint32_t addr) {
    asm volatile("ldmatrix.sync.aligned.m8n8.x4.shared.b16 {%0,%1,%2,%3}, [%4];"
        : "=r"(r[0]), "=r"(r[1]), "=r"(r[2]), "=r"(r[3]) : "r"(addr));
}
__device__ __forceinline__ void mma_f16(float (&d)[4], const uint32_t (&a)[4],
                                        uint32_t b0, uint32_t b1) {
    asm volatile(
        "mma.sync.aligned.m16n8k16.row.col.f32.f16.f16.f32 "
        "{%0,%1,%2,%3}, {%4,%5,%6,%7}, {%8,%9}, {%0,%1,%2,%3};"
        : "+f"(d[0]), "+f"(d[1]), "+f"(d[2]), "+f"(d[3])
        : "r"(a[0]), "r"(a[1]), "r"(a[2]), "r"(a[3]), "r"(b0), "r"(b1));
}
#define SW128(o) ((o) ^ (((o) >> 3) & 0x70))

// ---------------------------------------------------------------------------
// conv Q: fp32 -> (hi, lo) fp16
// ---------------------------------------------------------------------------
__global__ __launch_bounds__(256) void conv_q(const float* __restrict__ x) {
    size_t i = ((size_t)blockIdx.x * 256 + threadIdx.x) * 4;
    float4 v = *(const float4*)(x + i);
    __half h0 = __float2half_rn(v.x), h1 = __float2half_rn(v.y);
    __half h2 = __float2half_rn(v.z), h3 = __float2half_rn(v.w);
    __half l0 = __float2half_rn(v.x - __half2float(h0));
    __half l1 = __float2half_rn(v.y - __half2float(h1));
    __half l2 = __float2half_rn(v.z - __half2float(h2));
    __half l3 = __float2half_rn(v.w - __half2float(h3));
    __half2 hp0(h0, h1), hp1(h2, h3), lp0(l0, l1), lp1(l2, l3);
    *(uint2*)(g_Qhi + i) = make_uint2(*(uint32_t*)&hp0, *(uint32_t*)&hp1);
    *(uint2*)(g_Qlo + i) = make_uint2(*(uint32_t*)&lp0, *(uint32_t*)&lp1);
}

// conv K: fp32 -> fp16 single
__global__ __launch_bounds__(256) void conv_k(const float* __restrict__ x) {
    size_t i = ((size_t)blockIdx.x * 256 + threadIdx.x) * 4;
    float4 v = *(const float4*)(x + i);
    __half2 p0 = __floats2half2_rn(v.x, v.y);
    __half2 p1 = __floats2half2_rn(v.z, v.w);
    *(uint2*)(g_Kf16 + i) = make_uint2(*(uint32_t*)&p0, *(uint32_t*)&p1);
}

// ---------------------------------------------------------------------------
// vtrans: V [b][s][d] -> V^T fp16 [b][d][s]
// ---------------------------------------------------------------------------
__global__ __launch_bounds__(256) void vtrans(const float* __restrict__ V) {
    __shared__ float tile[32][33];
    int b = blockIdx.z, s0 = blockIdx.y * 32, d0 = blockIdx.x * 32;
    int t = threadIdx.x;
    int r = t >> 3, c4 = t & 7;
    const float* Vb = V + ((size_t)b * TSEQ + s0) * DDIM + d0;
    float4 v = *(const float4*)(Vb + (size_t)r * DDIM + c4 * 4);
    tile[r][c4 * 4 + 0] = v.x; tile[r][c4 * 4 + 1] = v.y;
    tile[r][c4 * 4 + 2] = v.z; tile[r][c4 * 4 + 3] = v.w;
    __syncthreads();
    int dr = t >> 3, s4 = t & 7;
    float x0 = tile[s4 * 4 + 0][dr], x1 = tile[s4 * 4 + 1][dr];
    float x2 = tile[s4 * 4 + 2][dr], x3 = tile[s4 * 4 + 3][dr];
    __half2 p0 = __floats2half2_rn(x0, x1);
    __half2 p1 = __floats2half2_rn(x2, x3);
    size_t off = ((size_t)b * DDIM + d0 + dr) * TSEQ + s0 + s4 * 4;
    *(uint2*)(g_Vtf16 + off) = make_uint2(*(uint32_t*)&p0, *(uint32_t*)&p1);
}

// ---------------------------------------------------------------------------
// QK^T: C[128,128] = Q[128,1024] K[128,1024]^T, fp16 2-term.
// 4-stage k64 pipeline (192KB smem: 3 bufs x 16KB per stage).
// 8 warps = 2m x 4n, warp tile 64x32. Epilogue: exp, rowsums, staged store.
// ---------------------------------------------------------------------------
#define QK_STAGE 49152
#define QK_SMEM  (4 * QK_STAGE + 2048)
#define QK_RED   (4 * QK_STAGE)

__global__ void __launch_bounds__(256, 1) qk_gemm(float* __restrict__ out) {
    extern __shared__ __align__(1024) char smem[];
    const uint32_t sb = smem_u32(smem);
    const int t = threadIdx.x, wid = t >> 5, lane = t & 31;
    const int tn = blockIdx.x, tm = blockIdx.y, b = blockIdx.z;

    const size_t aoff = ((size_t)b * TSEQ + tm * 128) * 1024;
    const size_t boff = ((size_t)b * TSEQ + tn * 128) * 1024;
    const __half* srcs[3] = {g_Qhi + aoff, g_Qlo + aoff, g_Kf16 + boff};

    const int lr = t >> 3;
    const int lc = t & 7;
    const uint32_t dsw = SW128((uint32_t)(lr * 128 + lc * 16));

    auto load_stage = [&](int slot, int k0) {
        const uint32_t s0 = sb + slot * QK_STAGE;
        #pragma unroll
        for (int buf = 0; buf < 3; buf++) {
            const __half* p = srcs[buf] + k0 + lc * 8;
            #pragma unroll
            for (int j = 0; j < 4; j++)
                cp16(s0 + buf * 16384 + dsw + j * 4096, p + (size_t)(lr + 32 * j) * 1024);
        }
        cp_commit();
    };

    const int warp_m = wid >> 2, warp_n = wid & 3;
    const int mrow = lane & 7, mid = lane >> 3;
    const int arow_base = warp_m * 64 + mrow + (mid & 1) * 8;
    const int a_k8 = mid >> 1;
    const int brow_base = warp_n * 32 + mrow + (mid >> 1) * 8;
    const int b_k8 = mid & 1;

    float acc[4][4][4] = {};

    load_stage(0, 0);
    load_stage(1, 64);
    load_stage(2, 128);

    for (int i = 0; i < 16; i++) {
        if (i < 14) cp_wait<2>(); else if (i == 14) cp_wait<1>(); else cp_wait<0>();
        __syncthreads();
        if (i + 3 < 16) load_stage((i + 3) & 3, (i + 3) * 64);   // slot freed at i-1

        const uint32_t sQh = sb + (i & 3) * QK_STAGE;
        const uint32_t sQl = sQh + 16384;
        const uint32_t sKh = sQh + 32768;

        #pragma unroll
        for (int ks = 0; ks < 4; ks++) {
            uint32_t ah[4][4], al[4][4], bh[2][4];
            #pragma unroll
            for (int mt = 0; mt < 4; mt++) {
                uint32_t off = SW128((uint32_t)((arow_base + mt * 16) * 128 + (ks * 2 + a_k8) * 16));
                ldsm4(ah[mt], sQh + off);
                ldsm4(al[mt], sQl + off);
            }
            #pragma unroll
            for (int np = 0; np < 2; np++) {
                uint32_t off = SW128((uint32_t)((brow_base + np * 16) * 128 + (ks * 2 + b_k8) * 16));
                ldsm4(bh[np], sKh + off);
            }
            #pragma unroll
            for (int mt = 0; mt < 4; mt++)
                #pragma unroll
                for (int nt = 0; nt < 4; nt++) {
                    const int np = nt >> 1, h = (nt & 1) * 2;
                    mma_f16(acc[mt][nt], ah[mt], bh[np][h], bh[np][h + 1]);
                    mma_f16(acc[mt][nt], al[mt], bh[np][h], bh[np][h + 1]);
                }
        }
    }

    __syncthreads();   // all MMA reads done; stage area reusable

    const int quad = lane >> 2, qid = lane & 3;
    float* stage = (float*)smem;                 // pitch 132 floats
    float* red = (float*)(smem + QK_RED);        // [128][4]

    float rs0[4] = {}, rs1[4] = {};
    #pragma unroll
    for (int mt = 0; mt < 4; mt++) {
        const int r0 = warp_m * 64 + mt * 16 + quad;
        #pragma unroll
        for (int nt = 0; nt < 4; nt++) {
            const int c = warp_n * 32 + nt * 8 + qid * 2;
            float d0 = __expf(acc[mt][nt][0] * SCALE);
            float d1 = __expf(acc[mt][nt][1] * SCALE);
            float d2 = __expf(acc[mt][nt][2] * SCALE);
            float d3 = __expf(acc[mt][nt][3] * SCALE);
            rs0[mt] += d0 + d1; rs1[mt] += d2 + d3;
            *(float2*)&stage[r0 * 132 + c]       = make_float2(d0, d1);
            *(float2*)&stage[(r0 + 8) * 132 + c] = make_float2(d2, d3);
        }
    }
    #pragma unroll
    for (int mt = 0; mt < 4; mt++) {
        float s0 = rs0[mt], s1 = rs1[mt];
        s0 += __shfl_xor_sync(0xFFFFFFFFu, s0, 1);
        s0 += __shfl_xor_sync(0xFFFFFFFFu, s0, 2);
        s1 += __shfl_xor_sync(0xFFFFFFFFu, s1, 1);
        s1 += __shfl_xor_sync(0xFFFFFFFFu, s1, 2);
        if (qid == 0) {
            const int r0 = warp_m * 64 + mt * 16 + quad;
            red[r0 * 4 + warp_n] = s0;
            red[(r0 + 8) * 4 + warp_n] = s1;
        }
    }
    __syncthreads();

    if (t < 128) {
        float s = red[t * 4 + 0] + red[t * 4 + 1] + red[t * 4 + 2] + red[t * 4 + 3];
        g_rowpart[((size_t)b * TSEQ + tm * 128 + t) * NT + tn] = s;
    }

    float* op = out + ((size_t)b * TSEQ + tm * 128) * 1024 + tn * 128;
    const int j = t & 31;
    #pragma unroll
    for (int r = t >> 5; r < 128; r += 8) {
        float4 v = *(float4*)&stage[r * 132 + j * 4];
        *(float4*)(op + (size_t)r * 1024 + j * 4) = v;
    }
}

// ---------------------------------------------------------------------------
// P*V: O[128,128] = P[128,1024] Vt[128,1024]^T, fp16 single-pass.
// 2-stage k64 (64KB smem), 2 CTAs/SM, direct register->gmem epilogue.
// ---------------------------------------------------------------------------
#define PV_SMEM 65536

__global__ void __launch_bounds__(256, 2) pv_gemm(float* __restrict__ out) {
    extern __shared__ __align__(1024) char smem[];
    const uint32_t sb = smem_u32(smem);
    const int t = threadIdx.x, wid = t >> 5, lane = t & 31;
    const int tn = blockIdx.x, tm = blockIdx.y, b = blockIdx.z;

    const __half* srcs[2] = {
        g_Pf16  + ((size_t)b * TSEQ + tm * 128) * 1024,
        g_Vtf16 + ((size_t)b * DDIM + tn * 128) * 1024
    };

    const int lr = t >> 3;
    const int lc = t & 7;
    const uint32_t dsw = SW128((uint32_t)(lr * 128 + lc * 16));

    auto load_stage = [&](int slot, int k0) {
        const uint32_t s0 = sb + slot * 32768;
        #pragma unroll
        for (int buf = 0; buf < 2; buf++) {
            const __half* p = srcs[buf] + k0 + lc * 8;
            #pragma unroll
            for (int j = 0; j < 4; j++)
                cp16(s0 + buf * 16384 + dsw + j * 4096, p + (size_t)(lr + 32 * j) * 1024);
        }
        cp_commit();
    };

    const int warp_m = wid >> 2, warp_n = wid & 3;
    const int mrow = lane & 7, mid = lane >> 3;
    const int arow_base = warp_m * 64 + mrow + (mid & 1) * 8;
    const int a_k8 = mid >> 1;
    const int brow_base = warp_n * 32 + mrow + (mid >> 1) * 8;
    const int b_k8 = mid & 1;

    float acc[4][4][4] = {};

    load_stage(0, 0);
    load_stage(1, 64);

    for (int i = 0; i < 16; i++) {
        if (i == 15) cp_wait<0>(); else cp_wait<1>();
        __syncthreads();

        const uint32_t sA = sb + (i & 1) * 32768;
        const uint32_t sB = sA + 16384;

        #pragma unroll
        for (int ks = 0; ks < 4; ks++) {
            uint32_t ah[4][4], bh[2][4];
            #pragma unroll
            for (int mt = 0; mt < 4; mt++) {
                uint32_t off = SW128((uint32_t)((arow_base + mt * 16) * 128 + (ks * 2 + a_k8) * 16));
                ldsm4(ah[mt], sA + off);
            }
            #pragma unroll
            for (int np = 0; np < 2; np++) {
                uint32_t off = SW128((uint32_t)((brow_base + np * 16) * 128 + (ks * 2 + b_k8) * 16));
                ldsm4(bh[np], sB + off);
            }
            #pragma unroll
            for (int mt = 0; mt < 4; mt++)
                #pragma unroll
                for (int nt = 0; nt < 4; nt++) {
                    const int np = nt >> 1, h = (nt & 1) * 2;
                    mma_f16(acc[mt][nt], ah[mt], bh[np][h], bh[np][h + 1]);
                }
        }

        __syncthreads();
        if (i + 2 < 16) load_stage(i & 1, (i + 2) * 64);
    }

    // direct register -> gmem epilogue
    const int quad = lane >> 2, qid = lane & 3;
    float* op = out + ((size_t)b * TSEQ + tm * 128) * 1024 + tn * 128;
    #pragma unroll
    for (int mt = 0; mt < 4; mt++) {
        const int r0 = warp_m * 64 + mt * 16 + quad;
        #pragma unroll
        for (int nt = 0; nt < 4; nt++) {
            const int c = warp_n * 32 + nt * 8 + qid * 2;
            *(float2*)(op + (size_t)r0 * 1024 + c)       = make_float2(acc[mt][nt][0], acc[mt][nt][1]);
            *(float2*)(op + (size_t)(r0 + 8) * 1024 + c) = make_float2(acc[mt][nt][2], acc[mt][nt][3]);
        }
    }
}

// ---------------------------------------------------------------------------
// norm: scores /= rowsum (fp32 in place), emit fp16 P
// ---------------------------------------------------------------------------
__global__ __launch_bounds__(256) void norm_kernel(float* __restrict__ scores) {
    const int row = blockIdx.x;
    __shared__ float sinv;
    if (threadIdx.x < 8) {
        float s = g_rowpart[(size_t)row * NT + threadIdx.x];
        #pragma unroll
        for (int o = 4; o > 0; o >>= 1) s += __shfl_xor_sync(0xFFu, s, o);
        if (threadIdx.x == 0) sinv = 1.0f / s;
    }
    __syncthreads();
    const float inv = sinv;
    const size_t base = (size_t)row * TSEQ + threadIdx.x * 4;
    float4 v = *(float4*)(scores + base);
    v.x *= inv; v.y *= inv; v.z *= inv; v.w *= inv;
    *(float4*)(scores + base) = v;
    __half2 p0 = __floats2half2_rn(v.x, v.y);
    __half2 p1 = __floats2half2_rn(v.z, v.w);
    *(uint2*)(g_Pf16 + base) = make_uint2(*(uint32_t*)&p0, *(uint32_t*)&p1);
}

// ---------------------------------------------------------------------------
extern "C" void kernel_launch(void* const* d_in, const int* in_sizes, int n_in,
                              void* d_out, int out_size)
{
    const float* Q = (const float*)d_in[0];
    const float* K = (const float*)d_in[1];
    const float* V = (const float*)d_in[2];
    float* summaries = (float*)d_out;
    float* scores    = (float*)d_out + NELEM;

    cudaFuncSetAttribute(qk_gemm, cudaFuncAttributeMaxDynamicSharedMemorySize, QK_SMEM);
    cudaFuncSetAttribute(pv_gemm, cudaFuncAttributeMaxDynamicSharedMemorySize, PV_SMEM);

    const int cblocks = (int)(NELEM / (256 * 4));
    conv_q<<<cblocks, 256>>>(Q);
    conv_k<<<cblocks, 256>>>(K);
    vtrans<<<dim3(32, 32, 16), 256>>>(V);

    dim3 ggrid(8, 8, 16);
    qk_gemm<<<ggrid, 256, QK_SMEM>>>(scores);
    norm_kernel<<<BATCH * TSEQ, 256>>>(scores);
    pv_gemm<<<ggrid, 256, PV_SMEM>>>(summaries);
}